// round 2
// baseline (speedup 1.0000x reference)
#include <cuda_runtime.h>
#include <cstdint>
#include <cstddef>

// Problem constants (fixed by the dataset)
#define B_  32
#define N_  1024
#define D_  128
#define C_  16
// P*P = 16, Hg = 32, out image 128x128 per (b,c)

// Tiling
#define NT      64    // n rows per block
#define THREADS 256   // thread = (n_local 0..63, p-quarter 0..3)
#define XPAD    4     // shared row pad (floats): row stride 132*4=528B, 528%128=16 -> conflict-free LDS.128

// Shared layout (floats)
#define SX_OFF    0                    // [64][132]
#define SW_OFF    (NT * (D_ + XPAD))   // 8448: [16][128]
#define SCBM_OFF  (SW_OFF + 16 * D_)   // 10496: [16][16]
#define SMASK_OFF (SCBM_OFF + 256)     // 10752: [16]
#define SMEM_FLOATS (SMASK_OFF + 16)   // 10768
#define SMEM_BYTES  (SMEM_FLOATS * 4)  // 43072

__device__ __forceinline__ uint32_t smem_u32(const void* p) {
    return (uint32_t)__cvta_generic_to_shared(p);
}

__global__ void __launch_bounds__(THREADS, 4)
QueryBasedDecoder_37546604102322_kernel(
    const float* __restrict__ x,     // [B, N, D]
    const float* __restrict__ pmask, // [B, C]
    const float* __restrict__ emb,   // [256, D] (only first C rows used)
    const float* __restrict__ W,     // [16, D]
    const float* __restrict__ bias,  // [16]
    float* __restrict__ out)         // [B, C, 128, 128]
{
    extern __shared__ float sm[];
    float* sx    = sm + SX_OFF;
    float* sw    = sm + SW_OFF;
    float* scbm  = sm + SCBM_OFF;
    float* smask = sm + SMASK_OFF;

    const int b  = blockIdx.y;
    const int n0 = blockIdx.x * NT;
    const int t  = threadIdx.x;

    // ---- Stage x tile (64 rows x 128 floats = 32KB contiguous in GMEM) via cp.async ----
    const float4* gx = reinterpret_cast<const float4*>(x + ((size_t)b * N_ + n0) * D_);
    #pragma unroll
    for (int i = 0; i < 8; ++i) {
        int k = t + THREADS * i;                 // chunk 0..2047: row = k>>5, col16 = k&31
        uint32_t dst = smem_u32(sx + (k >> 5) * (D_ + XPAD) + (k & 31) * 4);
        asm volatile("cp.async.cg.shared.global [%0], [%1], 16;\n"
                     :: "r"(dst), "l"(gx + k));
    }
    // ---- Stage W (16x128 floats = 512 chunks) ----
    const float4* gw = reinterpret_cast<const float4*>(W);
    #pragma unroll
    for (int i = 0; i < 2; ++i) {
        int k = t + THREADS * i;
        uint32_t dst = smem_u32(sw + k * 4);
        asm volatile("cp.async.cg.shared.global [%0], [%1], 16;\n"
                     :: "r"(dst), "l"(gw + k));
    }
    asm volatile("cp.async.commit_group;\n");

    // ---- Channel table, overlapped with the async copies (reads are L2-hot):
    //      cbm[c][p] = (emb[c]·W[p] + bias[p]) * mask[b][c]  (one entry per thread) ----
    {
        const int c = t >> 4, p = t & 15;
        const float4* ev = reinterpret_cast<const float4*>(emb + (size_t)c * D_);
        const float4* wv = reinterpret_cast<const float4*>(W + (size_t)p * D_);
        float s = 0.f;
        #pragma unroll
        for (int i = 0; i < 32; ++i) {
            float4 a = ev[i], w4 = wv[i];
            s = fmaf(a.x, w4.x, s);
            s = fmaf(a.y, w4.y, s);
            s = fmaf(a.z, w4.z, s);
            s = fmaf(a.w, w4.w, s);
        }
        float m = pmask[b * C_ + c];
        scbm[t] = (s + bias[p]) * m;
        if (p == 0) smask[c] = m;
    }

    asm volatile("cp.async.wait_group 0;\n");
    __syncthreads();

    // ---- Main dot products: xa[n][p] for this thread's (n_local, 4 p's = one patch row) ----
    const int nl = t & 63;
    const int q  = t >> 6;                       // patch row pr = q; p = q*4 + j
    const float* xr = sx + nl * (D_ + XPAD);
    const float* wr = sw + q * 4 * D_;

    float acc[4] = {0.f, 0.f, 0.f, 0.f};

    #pragma unroll
    for (int d4 = 0; d4 < 32; ++d4) {
        float4 xv = *reinterpret_cast<const float4*>(xr + d4 * 4);  // conflict-free (pad)
        #pragma unroll
        for (int j = 0; j < 4; ++j) {
            float4 wv = *reinterpret_cast<const float4*>(wr + j * D_ + d4 * 4);  // warp-broadcast
            acc[j] = fmaf(xv.x, wv.x, acc[j]);
            acc[j] = fmaf(xv.y, wv.y, acc[j]);
            acc[j] = fmaf(xv.z, wv.z, acc[j]);
            acc[j] = fmaf(xv.w, wv.w, acc[j]);
        }
    }

    // ---- Epilogue: out[b][c][hg*4+q][wg*4 + j] = acc[j]*mask_c + cbm[c][q*4+j]
    //      One float4 store per channel; each warp's 32 lanes span wg=0..31 -> 512B contiguous ----
    const int n  = n0 + nl;
    const int hg = n >> 5, wg = n & 31;
    float* ob = out + (size_t)b * (C_ * 128 * 128) + (hg * 4 + q) * 128 + wg * 4;

    #pragma unroll
    for (int c = 0; c < C_; ++c) {
        float m = smask[c];
        float4 cb = *reinterpret_cast<const float4*>(scbm + c * 16 + q * 4);
        float4 v;
        v.x = fmaf(acc[0], m, cb.x);
        v.y = fmaf(acc[1], m, cb.y);
        v.z = fmaf(acc[2], m, cb.z);
        v.w = fmaf(acc[3], m, cb.w);
        *reinterpret_cast<float4*>(ob + c * (128 * 128)) = v;
    }
}

extern "C" void kernel_launch(void* const* d_in, const int* in_sizes, int n_in,
                              void* d_out, int out_size)
{
    const float* x    = (const float*)d_in[0];  // [32,1024,128]
    const float* pm   = (const float*)d_in[1];  // [32,16]
    const float* emb  = (const float*)d_in[2];  // [256,128]
    const float* W    = (const float*)d_in[3];  // [16,128]
    const float* bias = (const float*)d_in[4];  // [16]
    float* out        = (float*)d_out;          // [32,16,128,128]

    cudaFuncSetAttribute(QueryBasedDecoder_37546604102322_kernel,
                         cudaFuncAttributeMaxDynamicSharedMemorySize, SMEM_BYTES);

    dim3 grid(N_ / NT, B_);   // (16, 32) = 512 blocks
    dim3 block(THREADS);
    QueryBasedDecoder_37546604102322_kernel<<<grid, block, SMEM_BYTES>>>(
        x, pm, emb, W, bias, out);
}

// round 3
// speedup vs baseline: 2.1413x; 2.1413x over previous
#include <cuda_runtime.h>
#include <cstdint>
#include <cstddef>

// Problem constants (fixed by the dataset)
#define B_  32
#define N_  1024
#define D_  128
#define C_  16
// P*P = 16, Hg = 32, out image 128x128 per (b,c)

// Tiling
#define NT      128   // n rows per block
#define THREADS 256   // thread = (n_local 0..127, p-half 0..1)

// Shared layout (floats) — x tile uses XOR swizzle, no pad
#define SX_OFF    0                    // [128][128] swizzled, 64KB
#define SW_OFF    (NT * D_)            // 16384: [16][128]
#define SCBM_OFF  (SW_OFF + 16 * D_)   // 18432: [16][16] mask-premultiplied
#define SMASK_OFF (SCBM_OFF + 256)     // 18688: [16]
#define SMEM_FLOATS (SMASK_OFF + 16)   // 18704
#define SMEM_BYTES  (SMEM_FLOATS * 4)  // 74816 (~73.1KB -> 3 CTAs/SM)

// Precomputed channel table: cb[c*16+p] = emb[c]·W[p] + bias[p]
__device__ float g_cb[C_ * 16];

__device__ __forceinline__ uint32_t smem_u32(const void* p) {
    return (uint32_t)__cvta_generic_to_shared(p);
}

// ---------------------------------------------------------------------------
// Kernel A: build the 16x16 channel table once (one warp per entry).
// grid = 8 blocks x 1024 threads = 256 warps.
// ---------------------------------------------------------------------------
__global__ void __launch_bounds__(1024, 1)
cb_table_kernel(const float* __restrict__ emb,   // [256, D]
                const float* __restrict__ W,     // [16, D]
                const float* __restrict__ bias)  // [16]
{
    const int w = (blockIdx.x * blockDim.x + threadIdx.x) >> 5;  // 0..255
    const int l = threadIdx.x & 31;
    const int c = w >> 4, p = w & 15;

    float4 e = *reinterpret_cast<const float4*>(emb + (size_t)c * D_ + l * 4);
    float4 v = *reinterpret_cast<const float4*>(W   + (size_t)p * D_ + l * 4);
    float s = e.x * v.x + e.y * v.y + e.z * v.z + e.w * v.w;
    #pragma unroll
    for (int off = 16; off > 0; off >>= 1)
        s += __shfl_xor_sync(0xffffffffu, s, off);
    if (l == 0) g_cb[w] = s + bias[p];
}

// ---------------------------------------------------------------------------
// Kernel B: main fused decode.
// ---------------------------------------------------------------------------
__global__ void __launch_bounds__(THREADS, 3)
QueryBasedDecoder_37546604102322_kernel(
    const float* __restrict__ x,     // [B, N, D]
    const float* __restrict__ pmask, // [B, C]
    float* __restrict__ out)         // [B, C, 128, 128]
{
    extern __shared__ float sm[];
    float* sx    = sm + SX_OFF;
    float* sw    = sm + SW_OFF;
    float* scbm  = sm + SCBM_OFF;
    float* smask = sm + SMASK_OFF;

    const int b  = blockIdx.y;
    const int n0 = blockIdx.x * NT;
    const int t  = threadIdx.x;

    // ---- Stage x tile (128 rows x 128 floats = 64KB contiguous) via cp.async,
    //      XOR-swizzled: phys chunk col = c ^ (row & 7) (16B chunks) ----
    const float4* gx = reinterpret_cast<const float4*>(x + ((size_t)b * N_ + n0) * D_);
    #pragma unroll
    for (int i = 0; i < 16; ++i) {
        int k = t + THREADS * i;                 // 0..4095: row = k>>5, c = k&31
        int row = k >> 5, c = k & 31;
        uint32_t dst = smem_u32(sx + row * D_ + ((c ^ (row & 7)) << 2));
        asm volatile("cp.async.cg.shared.global [%0], [%1], 16;\n"
                     :: "r"(dst), "l"(gx + k));
    }
    // ---- Stage W (16x128 floats, linear) ----
    {
        // W lives right after x in... it doesn't; reuse gx? No — W comes via its own pointer.
    }
    asm volatile("cp.async.commit_group;\n");

    // ---- Load precomputed channel table (L2-hot, 1KB) + masks, overlapped ----
    {
        float m = pmask[b * C_ + (t >> 4)];
        scbm[t] = g_cb[t] * m;
        if (t < C_) smask[t] = pmask[b * C_ + t];
    }

    asm volatile("cp.async.wait_group 0;\n");
    __syncthreads();

    // ---- Main dot products: xa[n][p] for this thread's (n_local, 8 p's) ----
    const int nl   = t & 127;
    const int half = t >> 7;                     // 0: p=0..7, 1: p=8..15
    const float* xr = sx + nl * D_;
    const int xs = nl & 7;                       // swizzle key for this row
    const float* wr = sw + half * 8 * D_;

    float acc[8];
    #pragma unroll
    for (int j = 0; j < 8; ++j) acc[j] = 0.f;

    #pragma unroll
    for (int d4 = 0; d4 < 32; ++d4) {
        float4 xv = *reinterpret_cast<const float4*>(xr + ((d4 ^ xs) << 2));
        #pragma unroll
        for (int j = 0; j < 8; ++j) {
            float4 wv = *reinterpret_cast<const float4*>(wr + j * D_ + ((d4 ^ xs) << 2));
            acc[j] = fmaf(xv.x, wv.x, acc[j]);
            acc[j] = fmaf(xv.y, wv.y, acc[j]);
            acc[j] = fmaf(xv.z, wv.z, acc[j]);
            acc[j] = fmaf(xv.w, wv.w, acc[j]);
        }
    }

    // ---- Epilogue: out[b][c][hg*4 + half*2 + (j>>2)][wg*4 + (j&3)] ----
    const int n  = n0 + nl;
    const int hg = n >> 5, wg = n & 31;
    float* ob = out + (size_t)b * (C_ * 128 * 128)
                    + (hg * 4 + half * 2) * 128 + wg * 4;

    #pragma unroll
    for (int c = 0; c < C_; ++c) {
        float m = smask[c];
        float4 cb0 = *reinterpret_cast<const float4*>(scbm + c * 16 + half * 8);
        float4 cb1 = *reinterpret_cast<const float4*>(scbm + c * 16 + half * 8 + 4);
        float4 lo, hi;
        lo.x = fmaf(acc[0], m, cb0.x);
        lo.y = fmaf(acc[1], m, cb0.y);
        lo.z = fmaf(acc[2], m, cb0.z);
        lo.w = fmaf(acc[3], m, cb0.w);
        hi.x = fmaf(acc[4], m, cb1.x);
        hi.y = fmaf(acc[5], m, cb1.y);
        hi.z = fmaf(acc[6], m, cb1.z);
        hi.w = fmaf(acc[7], m, cb1.w);
        float* o = ob + c * (128 * 128);
        *reinterpret_cast<float4*>(o)       = lo;
        *reinterpret_cast<float4*>(o + 128) = hi;
    }
}

// Wrapper that also stages W — W must arrive via a kernel parameter, so the
// cp.async for W is issued in the same kernel (see body). To keep the main
// kernel signature clean we pass W here:
__global__ void __launch_bounds__(THREADS, 3)
dummy_unused() {}

extern "C" void kernel_launch(void* const* d_in, const int* in_sizes, int n_in,
                              void* d_out, int out_size);

// --- Real main kernel including W staging (replaces the above pattern) ---
__global__ void __launch_bounds__(THREADS, 3)
QBD_main_kernel(
    const float* __restrict__ x,     // [B, N, D]
    const float* __restrict__ pmask, // [B, C]
    const float* __restrict__ W,     // [16, D]
    float* __restrict__ out)         // [B, C, 128, 128]
{
    extern __shared__ float sm[];
    float* sx    = sm + SX_OFF;
    float* sw    = sm + SW_OFF;
    float* scbm  = sm + SCBM_OFF;
    float* smask = sm + SMASK_OFF;

    const int b  = blockIdx.y;
    const int n0 = blockIdx.x * NT;
    const int t  = threadIdx.x;

    // ---- Stage x tile, XOR-swizzled (16B chunk granularity) ----
    const float4* gx = reinterpret_cast<const float4*>(x + ((size_t)b * N_ + n0) * D_);
    #pragma unroll
    for (int i = 0; i < 16; ++i) {
        int k = t + THREADS * i;                 // 0..4095
        int row = k >> 5, c = k & 31;
        uint32_t dst = smem_u32(sx + row * D_ + ((c ^ (row & 7)) << 2));
        asm volatile("cp.async.cg.shared.global [%0], [%1], 16;\n"
                     :: "r"(dst), "l"(gx + k));
    }
    // ---- Stage W (16 rows x 128 floats), same swizzle keyed by W row & 7 ----
    const float4* gw = reinterpret_cast<const float4*>(W);
    #pragma unroll
    for (int i = 0; i < 2; ++i) {
        int k = t + THREADS * i;                 // 0..511: wrow = k>>5, c = k&31
        int wrow = k >> 5, c = k & 31;
        uint32_t dst = smem_u32(sw + wrow * D_ + ((c ^ (wrow & 7)) << 2));
        asm volatile("cp.async.cg.shared.global [%0], [%1], 16;\n"
                     :: "r"(dst), "l"(gw + k));
    }
    asm volatile("cp.async.commit_group;\n");

    // ---- Load precomputed channel table + masks (overlapped with cp.async) ----
    {
        float m = pmask[b * C_ + (t >> 4)];
        scbm[t] = g_cb[t] * m;
        if (t < C_) smask[t] = pmask[b * C_ + t];
    }

    asm volatile("cp.async.wait_group 0;\n");
    __syncthreads();

    // ---- Main dot products ----
    const int nl   = t & 127;
    const int half = t >> 7;
    const float* xr = sx + nl * D_;
    const int xs = nl & 7;
    const float* wr = sw + half * 8 * D_;

    float acc[8];
    #pragma unroll
    for (int j = 0; j < 8; ++j) acc[j] = 0.f;

    #pragma unroll
    for (int d4 = 0; d4 < 32; ++d4) {
        int xc = (d4 ^ xs) << 2;                 // this thread's swizzled chunk
        float4 xv = *reinterpret_cast<const float4*>(xr + xc);
        #pragma unroll
        for (int j = 0; j < 8; ++j) {
            int wrow = half * 8 + j;
            int wc = (d4 ^ (wrow & 7)) << 2;     // W swizzle (warp-uniform -> broadcast)
            float4 wv = *reinterpret_cast<const float4*>(sw + wrow * D_ + wc);
            acc[j] = fmaf(xv.x, wv.x, acc[j]);
            acc[j] = fmaf(xv.y, wv.y, acc[j]);
            acc[j] = fmaf(xv.z, wv.z, acc[j]);
            acc[j] = fmaf(xv.w, wv.w, acc[j]);
        }
    }
    (void)wr;

    // ---- Epilogue ----
    const int n  = n0 + nl;
    const int hg = n >> 5, wg = n & 31;
    float* ob = out + (size_t)b * (C_ * 128 * 128)
                    + (hg * 4 + half * 2) * 128 + wg * 4;

    #pragma unroll
    for (int c = 0; c < C_; ++c) {
        float m = smask[c];
        float4 cb0 = *reinterpret_cast<const float4*>(scbm + c * 16 + half * 8);
        float4 cb1 = *reinterpret_cast<const float4*>(scbm + c * 16 + half * 8 + 4);
        float4 lo, hi;
        lo.x = fmaf(acc[0], m, cb0.x);
        lo.y = fmaf(acc[1], m, cb0.y);
        lo.z = fmaf(acc[2], m, cb0.z);
        lo.w = fmaf(acc[3], m, cb0.w);
        hi.x = fmaf(acc[4], m, cb1.x);
        hi.y = fmaf(acc[5], m, cb1.y);
        hi.z = fmaf(acc[6], m, cb1.z);
        hi.w = fmaf(acc[7], m, cb1.w);
        float* o = ob + c * (128 * 128);
        *reinterpret_cast<float4*>(o)       = lo;
        *reinterpret_cast<float4*>(o + 128) = hi;
    }
}

extern "C" void kernel_launch(void* const* d_in, const int* in_sizes, int n_in,
                              void* d_out, int out_size)
{
    const float* x    = (const float*)d_in[0];  // [32,1024,128]
    const float* pm   = (const float*)d_in[1];  // [32,16]
    const float* emb  = (const float*)d_in[2];  // [256,128]
    const float* W    = (const float*)d_in[3];  // [16,128]
    const float* bias = (const float*)d_in[4];  // [16]
    float* out        = (float*)d_out;          // [32,16,128,128]

    // Kernel A: 256-entry channel table (one warp per entry)
    cb_table_kernel<<<8, 1024>>>(emb, W, bias);

    // Kernel B: main fused decode
    cudaFuncSetAttribute(QBD_main_kernel,
                         cudaFuncAttributeMaxDynamicSharedMemorySize, SMEM_BYTES);
    dim3 grid(N_ / NT, B_);   // (8, 32) = 256 blocks
    QBD_main_kernel<<<grid, THREADS, SMEM_BYTES>>>(x, pm, W, out);
}

// round 4
// speedup vs baseline: 2.1573x; 1.0075x over previous
#include <cuda_runtime.h>
#include <cstdint>
#include <cstddef>

// Problem constants (fixed by the dataset)
#define B_  32
#define N_  1024
#define D_  128
#define C_  16
// P*P = 16, Hg = 32, out image 128x128 per (b,c)

// Tiling: one thread per x row, all 16 p's per thread
#define NT      128
#define THREADS 128

// Shared layout (floats) — x tile XOR-swizzled at 16B-chunk granularity
#define SX_OFF    0                    // [128][128] swizzled, 64KB
#define SW_OFF    (NT * D_)            // 16384: [16][128] swizzled
#define SCBM_OFF  (SW_OFF + 16 * D_)   // 18432: [16][16] mask-premultiplied
#define SMASK_OFF (SCBM_OFF + 256)     // 18688: [16]
#define SMEM_FLOATS (SMASK_OFF + 16)   // 18704
#define SMEM_BYTES  (SMEM_FLOATS * 4)  // 74816 -> 3 CTAs/SM

// Precomputed channel table: cb[c*16+p] = emb[c]·W[p] + bias[p]
__device__ float g_cb[C_ * 16];

__device__ __forceinline__ uint32_t smem_u32(const void* p) {
    return (uint32_t)__cvta_generic_to_shared(p);
}

// Blackwell packed fp32x2 FMA (PTX-only; halves FFMA issue count)
#define FMA_F32X2(d, a, b, c) \
    asm("fma.rn.f32x2 %0, %1, %2, %3;" : "=l"(d) : "l"(a), "l"(b), "l"(c))

// ---------------------------------------------------------------------------
// Kernel A: build the 16x16 channel table once (one warp per entry).
// ---------------------------------------------------------------------------
__global__ void __launch_bounds__(1024, 1)
cb_table_kernel(const float* __restrict__ emb,   // [256, D]
                const float* __restrict__ W,     // [16, D]
                const float* __restrict__ bias)  // [16]
{
    const int w = (blockIdx.x * blockDim.x + threadIdx.x) >> 5;  // 0..255
    const int l = threadIdx.x & 31;
    const int c = w >> 4, p = w & 15;

    float4 e = *reinterpret_cast<const float4*>(emb + (size_t)c * D_ + l * 4);
    float4 v = *reinterpret_cast<const float4*>(W   + (size_t)p * D_ + l * 4);
    float s = e.x * v.x + e.y * v.y + e.z * v.z + e.w * v.w;
    #pragma unroll
    for (int off = 16; off > 0; off >>= 1)
        s += __shfl_xor_sync(0xffffffffu, s, off);
    if (l == 0) g_cb[w] = s + bias[p];
}

// ---------------------------------------------------------------------------
// Kernel B: main fused decode. One thread per token row; 16 packed accums.
// ---------------------------------------------------------------------------
__global__ void __launch_bounds__(THREADS, 3)
QBD_main_kernel(
    const float* __restrict__ x,     // [B, N, D]
    const float* __restrict__ pmask, // [B, C]
    const float* __restrict__ W,     // [16, D]
    float* __restrict__ out)         // [B, C, 128, 128]
{
    extern __shared__ float sm[];
    float* sx    = sm + SX_OFF;
    float* sw    = sm + SW_OFF;
    float* scbm  = sm + SCBM_OFF;
    float* smask = sm + SMASK_OFF;

    const int b  = blockIdx.y;
    const int n0 = blockIdx.x * NT;
    const int t  = threadIdx.x;

    // ---- Stage x tile (128x128 floats = 64KB contiguous) via cp.async,
    //      XOR-swizzled: phys 16B-chunk col = c ^ (row & 7) ----
    const float4* gx = reinterpret_cast<const float4*>(x + ((size_t)b * N_ + n0) * D_);
    #pragma unroll
    for (int i = 0; i < 32; ++i) {
        int k = t + THREADS * i;                 // 0..4095: row = k>>5, c = k&31
        int row = k >> 5, c = k & 31;
        uint32_t dst = smem_u32(sx + row * D_ + ((c ^ (row & 7)) << 2));
        asm volatile("cp.async.cg.shared.global [%0], [%1], 16;\n"
                     :: "r"(dst), "l"(gx + k));
    }
    // ---- Stage W (16x128 floats), same swizzle keyed by W row & 7 ----
    const float4* gw = reinterpret_cast<const float4*>(W);
    #pragma unroll
    for (int i = 0; i < 4; ++i) {
        int k = t + THREADS * i;                 // 0..511
        int wrow = k >> 5, c = k & 31;
        uint32_t dst = smem_u32(sw + wrow * D_ + ((c ^ (wrow & 7)) << 2));
        asm volatile("cp.async.cg.shared.global [%0], [%1], 16;\n"
                     :: "r"(dst), "l"(gw + k));
    }
    asm volatile("cp.async.commit_group;\n");

    // ---- Load precomputed channel table (1KB, L2-hot) + masks, overlapped ----
    {
        float m0 = pmask[b * C_ + (t >> 4)];
        float m1 = pmask[b * C_ + ((t + 128) >> 4)];
        scbm[t]       = g_cb[t] * m0;
        scbm[t + 128] = g_cb[t + 128] * m1;
        if (t < C_) smask[t] = pmask[b * C_ + t];
    }

    asm volatile("cp.async.wait_group 0;\n");
    __syncthreads();

    // ---- Main dot products: xa[n][p] for ALL 16 p's of this thread's row.
    //      Packed f32x2: acc2[j] holds (sum over even d, sum over odd d). ----
    const float* xr = sx + t * D_;
    const int    xs = t & 7;                     // swizzle key for this row

    unsigned long long acc2[16];
    #pragma unroll
    for (int j = 0; j < 16; ++j) acc2[j] = 0ull;

    #pragma unroll
    for (int d4 = 0; d4 < 32; ++d4) {
        // 16B = two packed f32x2 values
        ulonglong2 xv = *reinterpret_cast<const ulonglong2*>(xr + ((d4 ^ xs) << 2));
        #pragma unroll
        for (int j = 0; j < 16; ++j) {
            const ulonglong2 wv = *reinterpret_cast<const ulonglong2*>(
                sw + j * D_ + ((d4 ^ (j & 7)) << 2));   // warp-uniform -> broadcast
            FMA_F32X2(acc2[j], xv.x, wv.x, acc2[j]);
            FMA_F32X2(acc2[j], xv.y, wv.y, acc2[j]);
        }
    }

    // ---- Horizontal add (even+odd) then re-pack pairs for packed epilogue ----
    float xa[16];
    #pragma unroll
    for (int j = 0; j < 16; ++j) {
        uint32_t lo, hi;
        asm("mov.b64 {%0, %1}, %2;" : "=r"(lo), "=r"(hi) : "l"(acc2[j]));
        xa[j] = __uint_as_float(lo) + __uint_as_float(hi);
    }
    unsigned long long xa2[8];
    #pragma unroll
    for (int k = 0; k < 8; ++k)
        asm("mov.b64 %0, {%1, %2};" : "=l"(xa2[k])
            : "r"(__float_as_uint(xa[2 * k])), "r"(__float_as_uint(xa[2 * k + 1])));

    // ---- Epilogue: out[b][c][hg*4+pr][wg*4+pc] = xa[pr*4+pc]*m_c + cbm[c][...]
    //      Per (c,pr): one packed-FMA pair + one 16B store (512B/warp, coalesced) ----
    const int n  = n0 + t;
    const int hg = n >> 5, wg = n & 31;
    float* ob = out + (size_t)b * (C_ * 128 * 128) + hg * 4 * 128 + wg * 4;

    #pragma unroll
    for (int c = 0; c < C_; ++c) {
        float m = smask[c];
        unsigned long long m2;
        asm("mov.b64 %0, {%1, %1};" : "=l"(m2) : "r"(__float_as_uint(m)));
        float* oc = ob + c * (128 * 128);
        #pragma unroll
        for (int pr = 0; pr < 4; ++pr) {
            ulonglong2 cb = *reinterpret_cast<const ulonglong2*>(scbm + c * 16 + pr * 4);
            ulonglong2 v;
            FMA_F32X2(v.x, xa2[pr * 2],     m2, cb.x);
            FMA_F32X2(v.y, xa2[pr * 2 + 1], m2, cb.y);
            *reinterpret_cast<ulonglong2*>(oc + pr * 128) = v;
        }
    }
}

extern "C" void kernel_launch(void* const* d_in, const int* in_sizes, int n_in,
                              void* d_out, int out_size)
{
    const float* x    = (const float*)d_in[0];  // [32,1024,128]
    const float* pm   = (const float*)d_in[1];  // [32,16]
    const float* emb  = (const float*)d_in[2];  // [256,128]
    const float* W    = (const float*)d_in[3];  // [16,128]
    const float* bias = (const float*)d_in[4];  // [16]
    float* out        = (float*)d_out;          // [32,16,128,128]

    // Kernel A: 256-entry channel table (one warp per entry)
    cb_table_kernel<<<8, 1024>>>(emb, W, bias);

    // Kernel B: main fused decode
    cudaFuncSetAttribute(QBD_main_kernel,
                         cudaFuncAttributeMaxDynamicSharedMemorySize, SMEM_BYTES);
    dim3 grid(N_ / NT, B_);   // (8, 32) = 256 blocks
    QBD_main_kernel<<<grid, THREADS, SMEM_BYTES>>>(x, pm, W, out);
}